// round 14
// baseline (speedup 1.0000x reference)
#include <cuda_runtime.h>
#include <cuda_bf16.h>
#include <math.h>
#include <stdint.h>

// Problem constants
#define BSZ 4
#define TLEN 2048
#define CDIM 768
#define HN 12
#define DH 64
#define ROWSTRIDE (3*CDIM)   // 2304
#define MROWS (BSZ*TLEN)     // 8192

// ---------------------------------------------------------------------------
// Scratch
// ---------------------------------------------------------------------------
__device__ float g_qkv[(size_t)BSZ*TLEN*3*CDIM];           // [B,T,3C]
__device__ __nv_bfloat16 g_ah[(size_t)MROWS*CDIM];
__device__ __nv_bfloat16 g_al[(size_t)MROWS*CDIM];
__device__ __nv_bfloat16 g_wah[(size_t)(3*CDIM)*CDIM];
__device__ __nv_bfloat16 g_wal[(size_t)(3*CDIM)*CDIM];
__device__ __nv_bfloat16 g_wph[(size_t)CDIM*CDIM];
__device__ __nv_bfloat16 g_wpl[(size_t)CDIM*CDIM];
#define AHT ((size_t)BSZ*HN*TLEN*DH)
__device__ __nv_bfloat16 g_qh2[AHT];
__device__ __nv_bfloat16 g_ql2[AHT];
__device__ __nv_bfloat16 g_kh2[AHT];
__device__ __nv_bfloat16 g_kl2[AHT];
__device__ __nv_bfloat16 g_vth[AHT];
__device__ __nv_bfloat16 g_vtl[AHT];

// ---------------------------------------------------------------------------
// helpers
// ---------------------------------------------------------------------------
__device__ __forceinline__ uint32_t smem_u32(const void* p) {
    uint32_t a;
    asm("{ .reg .u64 t; cvta.to.shared.u64 t, %1; cvt.u32.u64 %0, t; }"
        : "=r"(a) : "l"(p));
    return a;
}
__device__ __forceinline__ void ldsm_x4(uint32_t& r0, uint32_t& r1,
                                        uint32_t& r2, uint32_t& r3,
                                        uint32_t addr) {
    asm volatile("ldmatrix.sync.aligned.m8n8.x4.shared.b16 {%0,%1,%2,%3}, [%4];"
                 : "=r"(r0), "=r"(r1), "=r"(r2), "=r"(r3) : "r"(addr));
}
__device__ __forceinline__ void mma_bf16(float& d0, float& d1, float& d2, float& d3,
                                         uint32_t a0, uint32_t a1, uint32_t a2, uint32_t a3,
                                         uint32_t b0, uint32_t b1) {
    asm volatile(
        "mma.sync.aligned.m16n8k16.row.col.f32.bf16.bf16.f32 "
        "{%0,%1,%2,%3}, {%4,%5,%6,%7}, {%8,%9}, {%0,%1,%2,%3};"
        : "+f"(d0), "+f"(d1), "+f"(d2), "+f"(d3)
        : "r"(a0), "r"(a1), "r"(a2), "r"(a3), "r"(b0), "r"(b1));
}
__device__ __forceinline__ float ex2f(float x) {
    float r; asm("ex2.approx.ftz.f32 %0, %1;" : "=f"(r) : "f"(x)); return r;
}
__device__ __forceinline__ void split2(float x, float y, uint32_t& hi, uint32_t& lo) {
    __nv_bfloat162 h = __floats2bfloat162_rn(x, y);
    __nv_bfloat162 l = __floats2bfloat162_rn(x - __low2float(h), y - __high2float(h));
    hi = *reinterpret_cast<uint32_t*>(&h);
    lo = *reinterpret_cast<uint32_t*>(&l);
}
__device__ __forceinline__ void cp_async16(uint32_t dst, const void* src) {
    asm volatile("cp.async.ca.shared.global [%0], [%1], 16;"
                 :: "r"(dst), "l"(src));
}
// XOR swizzle for 64-byte rows (validated in R10): 16B chunk ^= (row>>1)&3
__device__ __forceinline__ uint32_t swz64(uint32_t off) {
    return off ^ (((off >> 7) & 3u) << 4);
}

// ---------------------------------------------------------------------------
// fp32 -> (hi, lo) bf16 split, elementwise
// ---------------------------------------------------------------------------
__global__ __launch_bounds__(256) void split_kernel(
    const float* __restrict__ in, __nv_bfloat16* __restrict__ hi,
    __nv_bfloat16* __restrict__ lo, int n4)
{
    int i = blockIdx.x * blockDim.x + threadIdx.x;
    if (i >= n4) return;
    float4 v = reinterpret_cast<const float4*>(in)[i];
    __nv_bfloat162 h01 = __floats2bfloat162_rn(v.x, v.y);
    __nv_bfloat162 h23 = __floats2bfloat162_rn(v.z, v.w);
    reinterpret_cast<__nv_bfloat162*>(hi)[i*2]   = h01;
    reinterpret_cast<__nv_bfloat162*>(hi)[i*2+1] = h23;
    __nv_bfloat162 l01 = __floats2bfloat162_rn(v.x - __low2float(h01), v.y - __high2float(h01));
    __nv_bfloat162 l23 = __floats2bfloat162_rn(v.z - __low2float(h23), v.w - __high2float(h23));
    reinterpret_cast<__nv_bfloat162*>(lo)[i*2]   = l01;
    reinterpret_cast<__nv_bfloat162*>(lo)[i*2+1] = l23;
}

// ---------------------------------------------------------------------------
// W[K,N] fp32 -> Wt hi/lo [N,K] bf16 (transpose + split)
// ---------------------------------------------------------------------------
__global__ __launch_bounds__(256) void transpose_split_kernel(
    const float* __restrict__ W, __nv_bfloat16* __restrict__ th,
    __nv_bfloat16* __restrict__ tl, int K, int N)
{
    __shared__ float t[32][33];
    const int n0 = blockIdx.x * 32, k0 = blockIdx.y * 32;
    const int tx = threadIdx.x, ty0 = threadIdx.y;
#pragma unroll
    for (int i = 0; i < 4; i++) {
        int ty = ty0 + i*8;
        t[ty][tx] = W[(size_t)(k0 + ty) * N + n0 + tx];
    }
    __syncthreads();
#pragma unroll
    for (int i = 0; i < 4; i++) {
        int ty = ty0 + i*8;
        float v = t[tx][ty];
        __nv_bfloat16 h = __float2bfloat16(v);
        th[(size_t)(n0 + ty) * K + k0 + tx] = h;
        tl[(size_t)(n0 + ty) * K + k0 + tx] =
            __float2bfloat16(v - __bfloat162float(h));
    }
}

// ---------------------------------------------------------------------------
// qkv [B,T,3C] -> Q hi/lo (scaled by 0.125*log2e), K hi/lo as [B*H, T, 64]
// ---------------------------------------------------------------------------
__global__ __launch_bounds__(256) void split_qk_kernel(
    const float* __restrict__ qkv,
    __nv_bfloat16* __restrict__ Qh, __nv_bfloat16* __restrict__ Ql,
    __nv_bfloat16* __restrict__ Kh, __nv_bfloat16* __restrict__ Kl)
{
    int i = blockIdx.x * blockDim.x + threadIdx.x;
    if (i >= BSZ*TLEN*2*HN*16) return;
    int j = i;
    int d4 = j & 15; j >>= 4;
    int h  = j % HN; j /= HN;
    int s  = j & 1;  j >>= 1;
    int t  = j & (TLEN-1); j >>= 11;
    int b  = j;
    const float4 v = *reinterpret_cast<const float4*>(
        qkv + ((size_t)(b*TLEN + t))*ROWSTRIDE + s*CDIM + h*64 + d4*4);
    const float sc = s ? 1.0f : 0.18033688011112042f;  // 0.125*log2(e)
    float x0 = v.x*sc, x1 = v.y*sc, x2 = v.z*sc, x3 = v.w*sc;
    __nv_bfloat162 h01 = __floats2bfloat162_rn(x0, x1);
    __nv_bfloat162 h23 = __floats2bfloat162_rn(x2, x3);
    __nv_bfloat162 l01 = __floats2bfloat162_rn(x0 - __low2float(h01), x1 - __high2float(h01));
    __nv_bfloat162 l23 = __floats2bfloat162_rn(x2 - __low2float(h23), x3 - __high2float(h23));
    size_t dst = (((size_t)(b*HN + h))*TLEN + t)*64 + d4*4;
    __nv_bfloat16* H = s ? Kh : Qh;
    __nv_bfloat16* L = s ? Kl : Ql;
    *reinterpret_cast<__nv_bfloat162*>(H + dst)     = h01;
    *reinterpret_cast<__nv_bfloat162*>(H + dst + 2) = h23;
    *reinterpret_cast<__nv_bfloat162*>(L + dst)     = l01;
    *reinterpret_cast<__nv_bfloat162*>(L + dst + 2) = l23;
}

// ---------------------------------------------------------------------------
// V from qkv -> transposed [B*H, 64, T] hi/lo bf16
// ---------------------------------------------------------------------------
__global__ __launch_bounds__(256) void transpose_split_v_kernel(
    const float* __restrict__ qkv,
    __nv_bfloat16* __restrict__ Vh, __nv_bfloat16* __restrict__ Vl)
{
    __shared__ float t[32][33];
    const int bh = blockIdx.x;
    const int t0 = blockIdx.y * 32;
    const int d0 = blockIdx.z * 32;
    const int b = bh / HN, h = bh % HN;
    const int tx = threadIdx.x, ty0 = threadIdx.y;
#pragma unroll
    for (int i = 0; i < 4; i++) {
        int ty = ty0 + i*8;
        t[ty][tx] = qkv[((size_t)(b*TLEN + t0 + ty))*ROWSTRIDE + 2*CDIM + h*64 + d0 + tx];
    }
    __syncthreads();
#pragma unroll
    for (int i = 0; i < 4; i++) {
        int dy = ty0 + i*8;
        float v = t[tx][dy];
        __nv_bfloat16 hi = __float2bfloat16(v);
        size_t dst = ((size_t)bh*64 + d0 + dy)*TLEN + t0 + tx;
        Vh[dst] = hi;
        Vl[dst] = __float2bfloat16(v - __bfloat162float(hi));
    }
}

// ---------------------------------------------------------------------------
// HMMA split-bf16 GEMM v4: 128x128 CTA tile, 4 warps (2x2), warp tile 64x64,
// BK=32, XOR-swizzled smem (64B rows), 3-stage cp.async pipeline with
// R5-style issue-before-wait ordering, 2 syncs/chunk.
// ---------------------------------------------------------------------------
#define TILE_BYTES 8192                 // 128 rows x 64 bytes
#define STAGE_BYTES (4*TILE_BYTES)      // 32768
#define GEMM_SMEM_BYTES (3*STAGE_BYTES) // 98304 -> 2 CTA/SM

__global__ __launch_bounds__(128) void gemm_hmma_kernel(
    const __nv_bfloat16* __restrict__ Ah, const __nv_bfloat16* __restrict__ Al,
    const __nv_bfloat16* __restrict__ Bh, const __nv_bfloat16* __restrict__ Bl,
    const float* __restrict__ bias, float* __restrict__ Cm,
    int N, int K)
{
    extern __shared__ __nv_bfloat16 smem[];
    const uint32_t sbase = smem_u32(smem);
    const int tid  = threadIdx.x;
    const int wid  = tid >> 5;
    const int lane = tid & 31;
    const int bx = blockIdx.x, by = blockIdx.y;
    const int wm = wid & 1;
    const int wn = wid >> 1;

    const __nv_bfloat16* srcs[4];
    srcs[0] = Ah + (size_t)(by * 128) * K;
    srcs[1] = Al + (size_t)(by * 128) * K;
    srcs[2] = Bh + (size_t)(bx * 128) * K;
    srcs[3] = Bl + (size_t)(bx * 128) * K;

    const int lrw = tid >> 2;                        // base row (q*32 added)
    const int lcl = (tid & 3) * 8;                   // element col
    const uint32_t lc16 = (uint32_t)(tid & 3) * 16;  // byte col

    float d[4][8][4];
#pragma unroll
    for (int mt = 0; mt < 4; mt++)
#pragma unroll
        for (int nt = 0; nt < 8; nt++)
#pragma unroll
            for (int e = 0; e < 4; e++) d[mt][nt][e] = 0.0f;

    const int KC = K / 32;

    auto load_stage = [&](int kc, int buf) {
        const int k0 = kc * 32;
        const uint32_t sdst = sbase + (uint32_t)buf * STAGE_BYTES;
#pragma unroll
        for (int t = 0; t < 4; t++) {
            const __nv_bfloat16* base = srcs[t] + k0;
            const uint32_t tdst = sdst + (uint32_t)t * TILE_BYTES;
#pragma unroll
            for (int q = 0; q < 4; q++) {
                const int r = lrw + q * 32;
                const uint32_t off = swz64((uint32_t)r * 64u + lc16);
                cp_async16(tdst + off, base + (size_t)r * K + lcl);
            }
        }
        asm volatile("cp.async.commit_group;" ::: "memory");
    };

    load_stage(0, 0);
    load_stage(1, 1);

    const int a_r = (lane & 15);
    const int a_c = (lane >> 4) * 8;
    const int b_r = ((lane >> 4) & 1) * 8 + (lane & 7);
    const int b_c = ((lane >> 3) & 1) * 8;

    for (int c = 0; c < KC; c++) {
        // issue-before-wait (R5 ordering), 3-stage lookahead
        if (c + 2 < KC) {
            load_stage(c + 2, (c + 2) % 3);   // buf (c-1)%3, freed by last sync
            asm volatile("cp.async.wait_group 2;" ::: "memory");
        } else if (c + 1 < KC) {
            asm volatile("cp.async.wait_group 1;" ::: "memory");
        } else {
            asm volatile("cp.async.wait_group 0;" ::: "memory");
        }
        __syncthreads();

        const uint32_t sAh = sbase + (uint32_t)(c % 3) * STAGE_BYTES;
        const uint32_t sAl = sAh + TILE_BYTES;
        const uint32_t sBh = sAl + TILE_BYTES;
        const uint32_t sBl = sBh + TILE_BYTES;

#pragma unroll
        for (int kk = 0; kk < 32; kk += 16) {
            uint32_t ah[4][4], al[4][4];
#pragma unroll
            for (int mt = 0; mt < 4; mt++) {
                uint32_t off = swz64((uint32_t)(wm*64 + mt*16 + a_r) * 64u
                                     + (uint32_t)(kk + a_c) * 2u);
                ldsm_x4(ah[mt][0], ah[mt][1], ah[mt][2], ah[mt][3], sAh + off);
                ldsm_x4(al[mt][0], al[mt][1], al[mt][2], al[mt][3], sAl + off);
            }
            uint32_t bh[4][4], bl[4][4];
#pragma unroll
            for (int nt2 = 0; nt2 < 4; nt2++) {
                uint32_t off = swz64((uint32_t)(wn*64 + nt2*16 + b_r) * 64u
                                     + (uint32_t)(kk + b_c) * 2u);
                ldsm_x4(bh[nt2][0], bh[nt2][1], bh[nt2][2], bh[nt2][3], sBh + off);
                ldsm_x4(bl[nt2][0], bl[nt2][1], bl[nt2][2], bl[nt2][3], sBl + off);
            }
#pragma unroll
            for (int mt = 0; mt < 4; mt++) {
#pragma unroll
                for (int nt2 = 0; nt2 < 4; nt2++) {
                    float* d0 = d[mt][2*nt2];
                    float* d1 = d[mt][2*nt2+1];
                    mma_bf16(d0[0],d0[1],d0[2],d0[3],
                             ah[mt][0],ah[mt][1],ah[mt][2],ah[mt][3],
                             bh[nt2][0],bh[nt2][1]);
                    mma_bf16(d1[0],d1[1],d1[2],d1[3],
                             ah[mt][0],ah[mt][1],ah[mt][2],ah[mt][3],
                             bh[nt2][2],bh[nt2][3]);
                    mma_bf16(d0[0],d0[1],d0[2],d0[3],
                             ah[mt][0],ah[mt][1],ah[mt][2],ah[mt][3],
                             bl[nt2][0],bl[nt2][1]);
                    mma_bf16(d1[0],d1[1],d1[2],d1[3],
                             ah[mt][0],ah[mt][1],ah[mt][2],ah[mt][3],
                             bl[nt2][2],bl[nt2][3]);
                    mma_bf16(d0[0],d0[1],d0[2],d0[3],
                             al[mt][0],al[mt][1],al[mt][2],al[mt][3],
                             bh[nt2][0],bh[nt2][1]);
                    mma_bf16(d1[0],d1[1],d1[2],d1[3],
                             al[mt][0],al[mt][1],al[mt][2],al[mt][3],
                             bh[nt2][2],bh[nt2][3]);
                }
            }
        }
        __syncthreads();
    }

    const int row_base = by * 128 + wm * 64;
    const int col_base = bx * 128 + wn * 64;
    const int lr = lane >> 2;
    const int lc = (lane & 3) * 2;
#pragma unroll
    for (int mt = 0; mt < 4; mt++) {
        const int r0 = row_base + mt*16 + lr;
        const int r1 = r0 + 8;
#pragma unroll
        for (int nt = 0; nt < 8; nt++) {
            const int cc = col_base + nt*8 + lc;
            float b0 = __ldg(bias + cc), b1 = __ldg(bias + cc + 1);
            float2 o0; o0.x = d[mt][nt][0] + b0; o0.y = d[mt][nt][1] + b1;
            float2 o1; o1.x = d[mt][nt][2] + b0; o1.y = d[mt][nt][3] + b1;
            *reinterpret_cast<float2*>(Cm + (size_t)r0 * N + cc) = o0;
            *reinterpret_cast<float2*>(Cm + (size_t)r1 * N + cc) = o1;
        }
    }
}

// ---------------------------------------------------------------------------
// HMMA flash attention (causal) — round-7 artifact (frozen). O written as
// split bf16 directly into proj's A operand. Heavy q-tiles scheduled first.
// ---------------------------------------------------------------------------
#define ALD 72
#define ATTN_SMEM_BYTES ((2*128*ALD + 4*64*ALD) * 2)   // 73728

__global__ __launch_bounds__(128) void attn_mma_kernel(
    const __nv_bfloat16* __restrict__ Qh, const __nv_bfloat16* __restrict__ Ql,
    const __nv_bfloat16* __restrict__ Kh, const __nv_bfloat16* __restrict__ Kl,
    const __nv_bfloat16* __restrict__ Vh, const __nv_bfloat16* __restrict__ Vl,
    __nv_bfloat16* __restrict__ yh, __nv_bfloat16* __restrict__ yl)
{
    extern __shared__ __nv_bfloat16 sab[];
    __nv_bfloat16* sQh = sab;
    __nv_bfloat16* sQl = sQh + 128*ALD;
    __nv_bfloat16* sKh = sQl + 128*ALD;
    __nv_bfloat16* sKl = sKh + 64*ALD;
    __nv_bfloat16* sVh = sKl + 64*ALD;
    __nv_bfloat16* sVl = sVh + 64*ALD;

    const int tid = threadIdx.x, lane = tid & 31, wm = tid >> 5;
    const int qt = (gridDim.x - 1) - blockIdx.x;   // heavy blocks first
    const int bh = blockIdx.y;
    const int b = bh / HN, h = bh % HN;

    const size_t qoff = ((size_t)bh * TLEN + (size_t)qt*128) * 64;
#pragma unroll
    for (int i = 0; i < 8; i++) {
        int idx = tid + i*128;
        int r = idx >> 3, c = (idx & 7) * 8;
        *reinterpret_cast<uint4*>(sQh + r*ALD + c) =
            *reinterpret_cast<const uint4*>(Qh + qoff + (size_t)r*64 + c);
        *reinterpret_cast<uint4*>(sQl + r*ALD + c) =
            *reinterpret_cast<const uint4*>(Ql + qoff + (size_t)r*64 + c);
    }

    float o[2][8][4];
#pragma unroll
    for (int mt = 0; mt < 2; mt++)
#pragma unroll
        for (int nt = 0; nt < 8; nt++)
#pragma unroll
            for (int e = 0; e < 4; e++) o[mt][nt][e] = 0.0f;

    const float NEG_INF = __int_as_float(0xff800000);
    float mrow[4] = {NEG_INF, NEG_INF, NEG_INF, NEG_INF};
    float lrow[4] = {0.0f, 0.0f, 0.0f, 0.0f};

    const int q0 = qt*128 + wm*32;
    const int a_r = lane & 15, a_c = (lane >> 4) * 8;
    const int b_r = ((lane >> 4) & 1) * 8 + (lane & 7);
    const int b_c = ((lane >> 3) & 1) * 8;
    const int lr = lane >> 2, lc2 = (lane & 3) * 2;

    const uint32_t uQh = smem_u32(sQh), uQl = smem_u32(sQl);
    const uint32_t uKh = smem_u32(sKh), uKl = smem_u32(sKl);
    const uint32_t uVh = smem_u32(sVh), uVl = smem_u32(sVl);

    const int ktiles = 2*qt + 2;
    for (int kt = 0; kt < ktiles; kt++) {
        const int kb = kt * 64;
        const size_t koff = ((size_t)bh * TLEN + kb) * 64;
        const size_t voff = (size_t)bh * 64 * TLEN + kb;
#pragma unroll
        for (int i = 0; i < 4; i++) {
            int idx = tid + i*128;
            int r = idx >> 3, c = (idx & 7) * 8;
            *reinterpret_cast<uint4*>(sKh + r*ALD + c) =
                *reinterpret_cast<const uint4*>(Kh + koff + (size_t)r*64 + c);
            *reinterpret_cast<uint4*>(sKl + r*ALD + c) =
                *reinterpret_cast<const uint4*>(Kl + koff + (size_t)r*64 + c);
            *reinterpret_cast<uint4*>(sVh + r*ALD + c) =
                *reinterpret_cast<const uint4*>(Vh + voff + (size_t)r*TLEN + c);
            *reinterpret_cast<uint4*>(sVl + r*ALD + c) =
                *reinterpret_cast<const uint4*>(Vl + voff + (size_t)r*TLEN + c);
        }
        __syncthreads();

        if (kb <= q0 + 31) {
            float s[2][8][4];
#pragma unroll
            for (int mt = 0; mt < 2; mt++)
#pragma unroll
                for (int nt = 0; nt < 8; nt++)
#pragma unroll
                    for (int e = 0; e < 4; e++) s[mt][nt][e] = 0.0f;

#pragma unroll
            for (int kk = 0; kk < 64; kk += 16) {
                uint32_t qh[2][4], ql[2][4];
#pragma unroll
                for (int mt = 0; mt < 2; mt++) {
                    uint32_t off = ((wm*32 + mt*16 + a_r) * ALD + kk + a_c) * 2;
                    ldsm_x4(qh[mt][0], qh[mt][1], qh[mt][2], qh[mt][3], uQh + off);
                    ldsm_x4(ql[mt][0], ql[mt][1], ql[mt][2], ql[mt][3], uQl + off);
                }
                uint32_t kh[4][4], kl[4][4];
#pragma unroll
                for (int nt2 = 0; nt2 < 4; nt2++) {
                    uint32_t off = ((nt2*16 + b_r) * ALD + kk + b_c) * 2;
                    ldsm_x4(kh[nt2][0], kh[nt2][1], kh[nt2][2], kh[nt2][3], uKh + off);
                    ldsm_x4(kl[nt2][0], kl[nt2][1], kl[nt2][2], kl[nt2][3], uKl + off);
                }
#pragma unroll
                for (int mt = 0; mt < 2; mt++) {
#pragma unroll
                    for (int nt2 = 0; nt2 < 4; nt2++) {
                        float* d0 = s[mt][2*nt2];
                        float* d1 = s[mt][2*nt2+1];
                        mma_bf16(d0[0],d0[1],d0[2],d0[3],
                                 qh[mt][0],qh[mt][1],qh[mt][2],qh[mt][3],
                                 kh[nt2][0],kh[nt2][1]);
                        mma_bf16(d1[0],d1[1],d1[2],d1[3],
                                 qh[mt][0],qh[mt][1],qh[mt][2],qh[mt][3],
                                 kh[nt2][2],kh[nt2][3]);
                        mma_bf16(d0[0],d0[1],d0[2],d0[3],
                                 qh[mt][0],qh[mt][1],qh[mt][2],qh[mt][3],
                                 kl[nt2][0],kl[nt2][1]);
                        mma_bf16(d1[0],d1[1],d1[2],d1[3],
                                 qh[mt][0],qh[mt][1],qh[mt][2],qh[mt][3],
                                 kl[nt2][2],kl[nt2][3]);
                        mma_bf16(d0[0],d0[1],d0[2],d0[3],
                                 ql[mt][0],ql[mt][1],ql[mt][2],ql[mt][3],
                                 kh[nt2][0],kh[nt2][1]);
                        mma_bf16(d1[0],d1[1],d1[2],d1[3],
                                 ql[mt][0],ql[mt][1],ql[mt][2],ql[mt][3],
                                 kh[nt2][2],kh[nt2][3]);
                    }
                }
            }

            if (kb + 63 > q0) {
#pragma unroll
                for (int mt = 0; mt < 2; mt++) {
                    const int r0 = q0 + mt*16 + lr;
#pragma unroll
                    for (int nt = 0; nt < 8; nt++) {
                        const int c0 = kb + nt*8 + lc2;
                        if (c0     > r0)     s[mt][nt][0] = NEG_INF;
                        if (c0 + 1 > r0)     s[mt][nt][1] = NEG_INF;
                        if (c0     > r0 + 8) s[mt][nt][2] = NEG_INF;
                        if (c0 + 1 > r0 + 8) s[mt][nt][3] = NEG_INF;
                    }
                }
            }

            float alpha[4];
#pragma unroll
            for (int mt = 0; mt < 2; mt++) {
#pragma unroll
                for (int hh = 0; hh < 2; hh++) {
                    const int e0 = hh*2;
                    const int id = mt*2 + hh;
                    float mx = NEG_INF;
#pragma unroll
                    for (int nt = 0; nt < 8; nt++)
                        mx = fmaxf(mx, fmaxf(s[mt][nt][e0], s[mt][nt][e0+1]));
                    mx = fmaxf(mx, __shfl_xor_sync(0xffffffffu, mx, 1));
                    mx = fmaxf(mx, __shfl_xor_sync(0xffffffffu, mx, 2));
                    const float mnew = fmaxf(mrow[id], mx);
                    const float al = ex2f(mrow[id] - mnew);
                    mrow[id] = mnew;
                    float ls = 0.0f;
#pragma unroll
                    for (int nt = 0; nt < 8; nt++) {
                        float p0 = ex2f(s[mt][nt][e0]   - mnew);
                        float p1 = ex2f(s[mt][nt][e0+1] - mnew);
                        s[mt][nt][e0]   = p0;
                        s[mt][nt][e0+1] = p1;
                        ls += p0 + p1;
                    }
                    ls += __shfl_xor_sync(0xffffffffu, ls, 1);
                    ls += __shfl_xor_sync(0xffffffffu, ls, 2);
                    lrow[id] = lrow[id] * al + ls;
                    alpha[id] = al;
                }
            }
#pragma unroll
            for (int mt = 0; mt < 2; mt++)
#pragma unroll
                for (int nt = 0; nt < 8; nt++) {
                    o[mt][nt][0] *= alpha[mt*2];
                    o[mt][nt][1] *= alpha[mt*2];
                    o[mt][nt][2] *= alpha[mt*2+1];
                    o[mt][nt][3] *= alpha[mt*2+1];
                }

#pragma unroll
            for (int kk = 0; kk < 4; kk++) {
                uint32_t vh[4][4], vl[4][4];
#pragma unroll
                for (int nt2 = 0; nt2 < 4; nt2++) {
                    uint32_t off = ((nt2*16 + b_r) * ALD + kk*16 + b_c) * 2;
                    ldsm_x4(vh[nt2][0], vh[nt2][1], vh[nt2][2], vh[nt2][3], uVh + off);
                    ldsm_x4(vl[nt2][0], vl[nt2][1], vl[nt2][2], vl[nt2][3], uVl + off);
                }
#pragma unroll
                for (int mt = 0; mt < 2; mt++) {
                    uint32_t ph[4], pl[4];
                    split2(s[mt][2*kk][0],   s[mt][2*kk][1],   ph[0], pl[0]);
                    split2(s[mt][2*kk][2],   s[mt][2*kk][3],   ph[1], pl[1]);
                    split2(s[mt][2*kk+1][0], s[mt][2*kk+1][1], ph[2], pl[2]);
                    split2(s[mt][2*kk+1][2], s[mt][2*kk+1][3], ph[3], pl[3]);
#pragma unroll
                    for (int nt2 = 0; nt2 < 4; nt2++) {
                        float* d0 = o[mt][2*nt2];
                        float* d1 = o[mt][2*nt2+1];
                        mma_bf16(d0[0],d0[1],d0[2],d0[3],
                                 ph[0],ph[1],ph[2],ph[3],
                                 vh[nt2][0],vh[nt2][1]);
                        mma_bf16(d1[0],d1[1],d1[2],d1[3],
                                 ph[0],ph[1],ph[2],ph[3],
                                 vh[nt2][2],vh[nt2][3]);
                        mma_bf16(d0[0],d0[1],d0[2],d0[3],
                                 ph[0],ph[1],ph[2],ph[3],
                                 vl[nt2][0],vl[nt2][1]);
                        mma_bf16(d1[0],d1[1],d1[2],d1[3],
                                 ph[0],ph[1],ph[2],ph[3],
                                 vl[nt2][2],vl[nt2][3]);
                        mma_bf16(d0[0],d0[1],d0[2],d0[3],
                                 pl[0],pl[1],pl[2],pl[3],
                                 vh[nt2][0],vh[nt2][1]);
                        mma_bf16(d1[0],d1[1],d1[2],d1[3],
                                 pl[0],pl[1],pl[2],pl[3],
                                 vh[nt2][2],vh[nt2][3]);
                    }
                }
            }
        }
        __syncthreads();
    }

    // ---- normalize + split-write O directly as proj's A operand ----
#pragma unroll
    for (int mt = 0; mt < 2; mt++) {
#pragma unroll
        for (int hh = 0; hh < 2; hh++) {
            const float inv = 1.0f / lrow[mt*2 + hh];
            const int row = qt*128 + wm*32 + mt*16 + lr + hh*8;
            const size_t base = ((size_t)(b*TLEN + row))*CDIM + h*64;
#pragma unroll
            for (int nt = 0; nt < 8; nt++) {
                uint32_t hi, lo;
                split2(o[mt][nt][hh*2] * inv, o[mt][nt][hh*2+1] * inv, hi, lo);
                *reinterpret_cast<uint32_t*>(yh + base + nt*8 + lc2) = hi;
                *reinterpret_cast<uint32_t*>(yl + base + nt*8 + lc2) = lo;
            }
        }
    }
}

// ---------------------------------------------------------------------------
// Launch
// ---------------------------------------------------------------------------
extern "C" void kernel_launch(void* const* d_in, const int* in_sizes, int n_in,
                              void* d_out, int out_size)
{
    (void)in_sizes; (void)n_in; (void)out_size;
    const float* x      = (const float*)d_in[0];
    const float* W_attn = (const float*)d_in[1];
    const float* b_attn = (const float*)d_in[2];
    const float* W_proj = (const float*)d_in[3];
    const float* b_proj = (const float*)d_in[4];
    float* out = (float*)d_out;

    float *qkv_ptr;
    __nv_bfloat16 *ah, *al, *wah, *wal, *wph, *wpl;
    __nv_bfloat16 *qh2, *ql2, *kh2, *kl2, *vth, *vtl;
    cudaGetSymbolAddress((void**)&qkv_ptr, g_qkv);
    cudaGetSymbolAddress((void**)&ah,  g_ah);
    cudaGetSymbolAddress((void**)&al,  g_al);
    cudaGetSymbolAddress((void**)&wah, g_wah);
    cudaGetSymbolAddress((void**)&wal, g_wal);
    cudaGetSymbolAddress((void**)&wph, g_wph);
    cudaGetSymbolAddress((void**)&wpl, g_wpl);
    cudaGetSymbolAddress((void**)&qh2, g_qh2);
    cudaGetSymbolAddress((void**)&ql2, g_ql2);
    cudaGetSymbolAddress((void**)&kh2, g_kh2);
    cudaGetSymbolAddress((void**)&kl2, g_kl2);
    cudaGetSymbolAddress((void**)&vth, g_vth);
    cudaGetSymbolAddress((void**)&vtl, g_vtl);

    static bool attr_set = false;
    if (!attr_set) {
        cudaFuncSetAttribute(gemm_hmma_kernel,
                             cudaFuncAttributeMaxDynamicSharedMemorySize,
                             GEMM_SMEM_BYTES);
        cudaFuncSetAttribute(attn_mma_kernel,
                             cudaFuncAttributeMaxDynamicSharedMemorySize,
                             ATTN_SMEM_BYTES);
        attr_set = true;
    }

    const int M = MROWS;

    // Prep: split x; transpose+split weights
    {
        int n4 = M * CDIM / 4;
        split_kernel<<<(n4 + 255)/256, 256>>>(x, ah, al, n4);
        dim3 tb(32, 8);
        transpose_split_kernel<<<dim3(3*CDIM/32, CDIM/32), tb>>>(W_attn, wah, wal, CDIM, 3*CDIM);
        transpose_split_kernel<<<dim3(CDIM/32, CDIM/32), tb>>>(W_proj, wph, wpl, CDIM, CDIM);
    }

    // 1) QKV GEMM
    gemm_hmma_kernel<<<dim3(3*CDIM/128, M/128), 128, GEMM_SMEM_BYTES>>>(
        ah, al, wah, wal, b_attn, qkv_ptr, 3*CDIM, CDIM);

    // 2) attention prep
    {
        int n = BSZ*TLEN*2*HN*16;
        split_qk_kernel<<<(n + 255)/256, 256>>>(qkv_ptr, qh2, ql2, kh2, kl2);
        dim3 tb(32, 8);
        transpose_split_v_kernel<<<dim3(BSZ*HN, TLEN/32, 2), tb>>>(qkv_ptr, vth, vtl);
    }

    // 3) flash attention (HMMA) -> split O straight into (g_ah, g_al)
    attn_mma_kernel<<<dim3(TLEN/128, BSZ*HN), 128, ATTN_SMEM_BYTES>>>(
        qh2, ql2, kh2, kl2, vth, vtl, ah, al);

    // 4) proj GEMM (full K, bias)
    gemm_hmma_kernel<<<dim3(CDIM/128, M/128), 128, GEMM_SMEM_BYTES>>>(
        ah, al, wph, wpl, b_proj, out, CDIM, CDIM);
}

// round 15
// speedup vs baseline: 1.0995x; 1.0995x over previous
#include <cuda_runtime.h>
#include <cuda_bf16.h>
#include <math.h>
#include <stdint.h>

// Problem constants
#define BSZ 4
#define TLEN 2048
#define CDIM 768
#define HN 12
#define DH 64
#define ROWSTRIDE (3*CDIM)   // 2304
#define MROWS (BSZ*TLEN)     // 8192

// ---------------------------------------------------------------------------
// Scratch
// ---------------------------------------------------------------------------
__device__ float g_qkv[(size_t)BSZ*TLEN*3*CDIM];           // [B,T,3C]
__device__ __nv_bfloat16 g_ah[(size_t)MROWS*CDIM];
__device__ __nv_bfloat16 g_al[(size_t)MROWS*CDIM];
__device__ __nv_bfloat16 g_wah[(size_t)(3*CDIM)*CDIM];
__device__ __nv_bfloat16 g_wal[(size_t)(3*CDIM)*CDIM];
__device__ __nv_bfloat16 g_wph[(size_t)CDIM*CDIM];
__device__ __nv_bfloat16 g_wpl[(size_t)CDIM*CDIM];
#define AHT ((size_t)BSZ*HN*TLEN*DH)
__device__ __nv_bfloat16 g_qh2[AHT];
__device__ __nv_bfloat16 g_ql2[AHT];
__device__ __nv_bfloat16 g_kh2[AHT];
__device__ __nv_bfloat16 g_kl2[AHT];
__device__ __nv_bfloat16 g_vth[AHT];
__device__ __nv_bfloat16 g_vtl[AHT];

// ---------------------------------------------------------------------------
// helpers
// ---------------------------------------------------------------------------
__device__ __forceinline__ uint32_t smem_u32(const void* p) {
    uint32_t a;
    asm("{ .reg .u64 t; cvta.to.shared.u64 t, %1; cvt.u32.u64 %0, t; }"
        : "=r"(a) : "l"(p));
    return a;
}
__device__ __forceinline__ void ldsm_x4(uint32_t& r0, uint32_t& r1,
                                        uint32_t& r2, uint32_t& r3,
                                        uint32_t addr) {
    asm volatile("ldmatrix.sync.aligned.m8n8.x4.shared.b16 {%0,%1,%2,%3}, [%4];"
                 : "=r"(r0), "=r"(r1), "=r"(r2), "=r"(r3) : "r"(addr));
}
__device__ __forceinline__ void mma_bf16(float& d0, float& d1, float& d2, float& d3,
                                         uint32_t a0, uint32_t a1, uint32_t a2, uint32_t a3,
                                         uint32_t b0, uint32_t b1) {
    asm volatile(
        "mma.sync.aligned.m16n8k16.row.col.f32.bf16.bf16.f32 "
        "{%0,%1,%2,%3}, {%4,%5,%6,%7}, {%8,%9}, {%0,%1,%2,%3};"
        : "+f"(d0), "+f"(d1), "+f"(d2), "+f"(d3)
        : "r"(a0), "r"(a1), "r"(a2), "r"(a3), "r"(b0), "r"(b1));
}
__device__ __forceinline__ float ex2f(float x) {
    float r; asm("ex2.approx.ftz.f32 %0, %1;" : "=f"(r) : "f"(x)); return r;
}
__device__ __forceinline__ void split2(float x, float y, uint32_t& hi, uint32_t& lo) {
    __nv_bfloat162 h = __floats2bfloat162_rn(x, y);
    __nv_bfloat162 l = __floats2bfloat162_rn(x - __low2float(h), y - __high2float(h));
    hi = *reinterpret_cast<uint32_t*>(&h);
    lo = *reinterpret_cast<uint32_t*>(&l);
}
__device__ __forceinline__ void cp_async16(uint32_t dst, const void* src) {
    asm volatile("cp.async.ca.shared.global [%0], [%1], 16;"
                 :: "r"(dst), "l"(src));
}

// ---------------------------------------------------------------------------
// fp32 -> (hi, lo) bf16 split, elementwise
// ---------------------------------------------------------------------------
__global__ __launch_bounds__(256) void split_kernel(
    const float* __restrict__ in, __nv_bfloat16* __restrict__ hi,
    __nv_bfloat16* __restrict__ lo, int n4)
{
    int i = blockIdx.x * blockDim.x + threadIdx.x;
    if (i >= n4) return;
    float4 v = reinterpret_cast<const float4*>(in)[i];
    __nv_bfloat162 h01 = __floats2bfloat162_rn(v.x, v.y);
    __nv_bfloat162 h23 = __floats2bfloat162_rn(v.z, v.w);
    reinterpret_cast<__nv_bfloat162*>(hi)[i*2]   = h01;
    reinterpret_cast<__nv_bfloat162*>(hi)[i*2+1] = h23;
    __nv_bfloat162 l01 = __floats2bfloat162_rn(v.x - __low2float(h01), v.y - __high2float(h01));
    __nv_bfloat162 l23 = __floats2bfloat162_rn(v.z - __low2float(h23), v.w - __high2float(h23));
    reinterpret_cast<__nv_bfloat162*>(lo)[i*2]   = l01;
    reinterpret_cast<__nv_bfloat162*>(lo)[i*2+1] = l23;
}

// ---------------------------------------------------------------------------
// W[K,N] fp32 -> Wt hi/lo [N,K] bf16 (transpose + split)
// ---------------------------------------------------------------------------
__global__ __launch_bounds__(256) void transpose_split_kernel(
    const float* __restrict__ W, __nv_bfloat16* __restrict__ th,
    __nv_bfloat16* __restrict__ tl, int K, int N)
{
    __shared__ float t[32][33];
    const int n0 = blockIdx.x * 32, k0 = blockIdx.y * 32;
    const int tx = threadIdx.x, ty0 = threadIdx.y;
#pragma unroll
    for (int i = 0; i < 4; i++) {
        int ty = ty0 + i*8;
        t[ty][tx] = W[(size_t)(k0 + ty) * N + n0 + tx];
    }
    __syncthreads();
#pragma unroll
    for (int i = 0; i < 4; i++) {
        int ty = ty0 + i*8;
        float v = t[tx][ty];
        __nv_bfloat16 h = __float2bfloat16(v);
        th[(size_t)(n0 + ty) * K + k0 + tx] = h;
        tl[(size_t)(n0 + ty) * K + k0 + tx] =
            __float2bfloat16(v - __bfloat162float(h));
    }
}

// ---------------------------------------------------------------------------
// qkv [B,T,3C] -> Q hi/lo (scaled by 0.125*log2e), K hi/lo as [B*H, T, 64]
// ---------------------------------------------------------------------------
__global__ __launch_bounds__(256) void split_qk_kernel(
    const float* __restrict__ qkv,
    __nv_bfloat16* __restrict__ Qh, __nv_bfloat16* __restrict__ Ql,
    __nv_bfloat16* __restrict__ Kh, __nv_bfloat16* __restrict__ Kl)
{
    int i = blockIdx.x * blockDim.x + threadIdx.x;
    if (i >= BSZ*TLEN*2*HN*16) return;
    int j = i;
    int d4 = j & 15; j >>= 4;
    int h  = j % HN; j /= HN;
    int s  = j & 1;  j >>= 1;
    int t  = j & (TLEN-1); j >>= 11;
    int b  = j;
    const float4 v = *reinterpret_cast<const float4*>(
        qkv + ((size_t)(b*TLEN + t))*ROWSTRIDE + s*CDIM + h*64 + d4*4);
    const float sc = s ? 1.0f : 0.18033688011112042f;  // 0.125*log2(e)
    float x0 = v.x*sc, x1 = v.y*sc, x2 = v.z*sc, x3 = v.w*sc;
    __nv_bfloat162 h01 = __floats2bfloat162_rn(x0, x1);
    __nv_bfloat162 h23 = __floats2bfloat162_rn(x2, x3);
    __nv_bfloat162 l01 = __floats2bfloat162_rn(x0 - __low2float(h01), x1 - __high2float(h01));
    __nv_bfloat162 l23 = __floats2bfloat162_rn(x2 - __low2float(h23), x3 - __high2float(h23));
    size_t dst = (((size_t)(b*HN + h))*TLEN + t)*64 + d4*4;
    __nv_bfloat16* H = s ? Kh : Qh;
    __nv_bfloat16* L = s ? Kl : Ql;
    *reinterpret_cast<__nv_bfloat162*>(H + dst)     = h01;
    *reinterpret_cast<__nv_bfloat162*>(H + dst + 2) = h23;
    *reinterpret_cast<__nv_bfloat162*>(L + dst)     = l01;
    *reinterpret_cast<__nv_bfloat162*>(L + dst + 2) = l23;
}

// ---------------------------------------------------------------------------
// V from qkv -> transposed [B*H, 64, T] hi/lo bf16
// ---------------------------------------------------------------------------
__global__ __launch_bounds__(256) void transpose_split_v_kernel(
    const float* __restrict__ qkv,
    __nv_bfloat16* __restrict__ Vh, __nv_bfloat16* __restrict__ Vl)
{
    __shared__ float t[32][33];
    const int bh = blockIdx.x;
    const int t0 = blockIdx.y * 32;
    const int d0 = blockIdx.z * 32;
    const int b = bh / HN, h = bh % HN;
    const int tx = threadIdx.x, ty0 = threadIdx.y;
#pragma unroll
    for (int i = 0; i < 4; i++) {
        int ty = ty0 + i*8;
        t[ty][tx] = qkv[((size_t)(b*TLEN + t0 + ty))*ROWSTRIDE + 2*CDIM + h*64 + d0 + tx];
    }
    __syncthreads();
#pragma unroll
    for (int i = 0; i < 4; i++) {
        int dy = ty0 + i*8;
        float v = t[tx][dy];
        __nv_bfloat16 hi = __float2bfloat16(v);
        size_t dst = ((size_t)bh*64 + d0 + dy)*TLEN + t0 + tx;
        Vh[dst] = hi;
        Vl[dst] = __float2bfloat16(v - __bfloat162float(hi));
    }
}

// ---------------------------------------------------------------------------
// HMMA split-bf16 GEMM (round-5 known-good, FROZEN): 128x128 CTA tile,
// 4 warps (2x2), warp tile 64x64, BK=32, LDP=40 padding, cp.async .ca
// 2-stage, issue-before-wait ordering.
// ---------------------------------------------------------------------------
#define LDP 40
#define TILE_ELEMS (128*LDP)
#define TILE_BYTES (TILE_ELEMS*2)
#define STAGE_BYTES (4*TILE_BYTES)
#define GEMM_SMEM_BYTES (2*STAGE_BYTES)   // 81920

__global__ __launch_bounds__(128) void gemm_hmma_kernel(
    const __nv_bfloat16* __restrict__ Ah, const __nv_bfloat16* __restrict__ Al,
    const __nv_bfloat16* __restrict__ Bh, const __nv_bfloat16* __restrict__ Bl,
    const float* __restrict__ bias, float* __restrict__ Cm,
    int N, int K)
{
    extern __shared__ __nv_bfloat16 smem[];
    const uint32_t sbase = smem_u32(smem);
    const int tid  = threadIdx.x;
    const int wid  = tid >> 5;
    const int lane = tid & 31;
    const int bx = blockIdx.x, by = blockIdx.y;
    const int wm = wid & 1;
    const int wn = wid >> 1;

    const __nv_bfloat16* srcs[4];
    srcs[0] = Ah + (size_t)(by * 128) * K;
    srcs[1] = Al + (size_t)(by * 128) * K;
    srcs[2] = Bh + (size_t)(bx * 128) * K;
    srcs[3] = Bl + (size_t)(bx * 128) * K;

    const int lrw = tid >> 2;
    const int lcl = (tid & 3) * 8;

    float d[4][8][4];
#pragma unroll
    for (int mt = 0; mt < 4; mt++)
#pragma unroll
        for (int nt = 0; nt < 8; nt++)
#pragma unroll
            for (int e = 0; e < 4; e++) d[mt][nt][e] = 0.0f;

    const int KC = K / 32;

    auto load_stage = [&](int kc, int buf) {
        const int k0 = kc * 32;
        const uint32_t sdst = sbase + (uint32_t)buf * STAGE_BYTES;
#pragma unroll
        for (int t = 0; t < 4; t++) {
            const __nv_bfloat16* base = srcs[t] + k0;
#pragma unroll
            for (int q = 0; q < 4; q++) {
                const int r = lrw + q * 32;
                const uint32_t dst = sdst + (uint32_t)t * TILE_BYTES
                                   + (uint32_t)(r * LDP + lcl) * 2;
                cp_async16(dst, base + (size_t)r * K + lcl);
            }
        }
        asm volatile("cp.async.commit_group;" ::: "memory");
    };

    load_stage(0, 0);

    const int a_r = (lane & 15);
    const int a_c = (lane >> 4) * 8;
    const int b_r = ((lane >> 4) & 1) * 8 + (lane & 7);
    const int b_c = ((lane >> 3) & 1) * 8;

    for (int c = 0; c < KC; c++) {
        const int cur = c & 1;
        if (c + 1 < KC) {
            load_stage(c + 1, cur ^ 1);
            asm volatile("cp.async.wait_group 1;" ::: "memory");
        } else {
            asm volatile("cp.async.wait_group 0;" ::: "memory");
        }
        __syncthreads();

        const uint32_t sAh = sbase + (uint32_t)cur * STAGE_BYTES;
        const uint32_t sAl = sAh + TILE_BYTES;
        const uint32_t sBh = sAl + TILE_BYTES;
        const uint32_t sBl = sBh + TILE_BYTES;

#pragma unroll
        for (int kk = 0; kk < 32; kk += 16) {
            uint32_t ah[4][4], al[4][4];
#pragma unroll
            for (int mt = 0; mt < 4; mt++) {
                uint32_t off = ((wm*64 + mt*16 + a_r) * LDP + kk + a_c) * 2;
                ldsm_x4(ah[mt][0], ah[mt][1], ah[mt][2], ah[mt][3], sAh + off);
                ldsm_x4(al[mt][0], al[mt][1], al[mt][2], al[mt][3], sAl + off);
            }
            uint32_t bh[4][4], bl[4][4];
#pragma unroll
            for (int nt2 = 0; nt2 < 4; nt2++) {
                uint32_t off = ((wn*64 + nt2*16 + b_r) * LDP + kk + b_c) * 2;
                ldsm_x4(bh[nt2][0], bh[nt2][1], bh[nt2][2], bh[nt2][3], sBh + off);
                ldsm_x4(bl[nt2][0], bl[nt2][1], bl[nt2][2], bl[nt2][3], sBl + off);
            }
#pragma unroll
            for (int mt = 0; mt < 4; mt++) {
#pragma unroll
                for (int nt2 = 0; nt2 < 4; nt2++) {
                    float* d0 = d[mt][2*nt2];
                    float* d1 = d[mt][2*nt2+1];
                    mma_bf16(d0[0],d0[1],d0[2],d0[3],
                             ah[mt][0],ah[mt][1],ah[mt][2],ah[mt][3],
                             bh[nt2][0],bh[nt2][1]);
                    mma_bf16(d1[0],d1[1],d1[2],d1[3],
                             ah[mt][0],ah[mt][1],ah[mt][2],ah[mt][3],
                             bh[nt2][2],bh[nt2][3]);
                    mma_bf16(d0[0],d0[1],d0[2],d0[3],
                             ah[mt][0],ah[mt][1],ah[mt][2],ah[mt][3],
                             bl[nt2][0],bl[nt2][1]);
                    mma_bf16(d1[0],d1[1],d1[2],d1[3],
                             ah[mt][0],ah[mt][1],ah[mt][2],ah[mt][3],
                             bl[nt2][2],bl[nt2][3]);
                    mma_bf16(d0[0],d0[1],d0[2],d0[3],
                             al[mt][0],al[mt][1],al[mt][2],al[mt][3],
                             bh[nt2][0],bh[nt2][1]);
                    mma_bf16(d1[0],d1[1],d1[2],d1[3],
                             al[mt][0],al[mt][1],al[mt][2],al[mt][3],
                             bh[nt2][2],bh[nt2][3]);
                }
            }
        }
        __syncthreads();
    }

    const int row_base = by * 128 + wm * 64;
    const int col_base = bx * 128 + wn * 64;
    const int lr = lane >> 2;
    const int lc = (lane & 3) * 2;
#pragma unroll
    for (int mt = 0; mt < 4; mt++) {
        const int r0 = row_base + mt*16 + lr;
        const int r1 = r0 + 8;
#pragma unroll
        for (int nt = 0; nt < 8; nt++) {
            const int cc = col_base + nt*8 + lc;
            float b0 = __ldg(bias + cc), b1 = __ldg(bias + cc + 1);
            float2 o0; o0.x = d[mt][nt][0] + b0; o0.y = d[mt][nt][1] + b1;
            float2 o1; o1.x = d[mt][nt][2] + b0; o1.y = d[mt][nt][3] + b1;
            *reinterpret_cast<float2*>(Cm + (size_t)r0 * N + cc) = o0;
            *reinterpret_cast<float2*>(Cm + (size_t)r1 * N + cc) = o1;
        }
    }
}

// ---------------------------------------------------------------------------
// HMMA flash attention (causal) — round-7 mainloop; K/V tile loads converted
// to single-buffer cp.async (LDGSTS: no register staging, same smem layout,
// same sync position). O written as split bf16 into proj's A operand.
// ---------------------------------------------------------------------------
#define ALD 72
#define KV_TENSOR_BYTES (64*ALD*2)   // 9216
#define ATTN_SMEM_BYTES ((2*128*ALD + 4*64*ALD) * 2)   // 73728

__global__ __launch_bounds__(128) void attn_mma_kernel(
    const __nv_bfloat16* __restrict__ Qh, const __nv_bfloat16* __restrict__ Ql,
    const __nv_bfloat16* __restrict__ Kh, const __nv_bfloat16* __restrict__ Kl,
    const __nv_bfloat16* __restrict__ Vh, const __nv_bfloat16* __restrict__ Vl,
    __nv_bfloat16* __restrict__ yh, __nv_bfloat16* __restrict__ yl)
{
    extern __shared__ __nv_bfloat16 sab[];
    __nv_bfloat16* sQh = sab;
    __nv_bfloat16* sQl = sQh + 128*ALD;
    __nv_bfloat16* sKh = sQl + 128*ALD;

    const int tid = threadIdx.x, lane = tid & 31, wm = tid >> 5;
    const int qt = (gridDim.x - 1) - blockIdx.x;   // heavy blocks first
    const int bh = blockIdx.y;
    const int b = bh / HN, h = bh % HN;

    const size_t qoff = ((size_t)bh * TLEN + (size_t)qt*128) * 64;
#pragma unroll
    for (int i = 0; i < 8; i++) {
        int idx = tid + i*128;
        int r = idx >> 3, c = (idx & 7) * 8;
        *reinterpret_cast<uint4*>(sQh + r*ALD + c) =
            *reinterpret_cast<const uint4*>(Qh + qoff + (size_t)r*64 + c);
        *reinterpret_cast<uint4*>(sQl + r*ALD + c) =
            *reinterpret_cast<const uint4*>(Ql + qoff + (size_t)r*64 + c);
    }

    float o[2][8][4];
#pragma unroll
    for (int mt = 0; mt < 2; mt++)
#pragma unroll
        for (int nt = 0; nt < 8; nt++)
#pragma unroll
            for (int e = 0; e < 4; e++) o[mt][nt][e] = 0.0f;

    const float NEG_INF = __int_as_float(0xff800000);
    float mrow[4] = {NEG_INF, NEG_INF, NEG_INF, NEG_INF};
    float lrow[4] = {0.0f, 0.0f, 0.0f, 0.0f};

    const int q0 = qt*128 + wm*32;
    const int a_r = lane & 15, a_c = (lane >> 4) * 8;
    const int b_r = ((lane >> 4) & 1) * 8 + (lane & 7);
    const int b_c = ((lane >> 3) & 1) * 8;
    const int lr = lane >> 2, lc2 = (lane & 3) * 2;

    const uint32_t uQh = smem_u32(sQh), uQl = smem_u32(sQl);
    const uint32_t uKh = smem_u32(sKh);
    const uint32_t uKl = uKh + KV_TENSOR_BYTES;
    const uint32_t uVh = uKl + KV_TENSOR_BYTES;
    const uint32_t uVl = uVh + KV_TENSOR_BYTES;

    // cp.async K/V loader coords: per i, rows r = (tid>>3)+i*16, col (tid&7)*8
    const int kv_r0 = tid >> 3;
    const int kv_c  = (tid & 7) * 8;

    const int ktiles = 2*qt + 2;
    for (int kt = 0; kt < ktiles; kt++) {
        const int kb = kt * 64;
        const size_t koff = ((size_t)bh * TLEN + kb) * 64;
        const size_t voff = (size_t)bh * 64 * TLEN + kb;
#pragma unroll
        for (int i = 0; i < 4; i++) {
            const int r = kv_r0 + i * 16;
            const uint32_t soff = (uint32_t)(r * ALD + kv_c) * 2;
            cp_async16(uKh + soff, Kh + koff + (size_t)r*64 + kv_c);
            cp_async16(uKl + soff, Kl + koff + (size_t)r*64 + kv_c);
            cp_async16(uVh + soff, Vh + voff + (size_t)r*TLEN + kv_c);
            cp_async16(uVl + soff, Vl + voff + (size_t)r*TLEN + kv_c);
        }
        asm volatile("cp.async.commit_group;" ::: "memory");
        asm volatile("cp.async.wait_group 0;" ::: "memory");
        __syncthreads();

        if (kb <= q0 + 31) {
            float s[2][8][4];
#pragma unroll
            for (int mt = 0; mt < 2; mt++)
#pragma unroll
                for (int nt = 0; nt < 8; nt++)
#pragma unroll
                    for (int e = 0; e < 4; e++) s[mt][nt][e] = 0.0f;

#pragma unroll
            for (int kk = 0; kk < 64; kk += 16) {
                uint32_t qh[2][4], ql[2][4];
#pragma unroll
                for (int mt = 0; mt < 2; mt++) {
                    uint32_t off = ((wm*32 + mt*16 + a_r) * ALD + kk + a_c) * 2;
                    ldsm_x4(qh[mt][0], qh[mt][1], qh[mt][2], qh[mt][3], uQh + off);
                    ldsm_x4(ql[mt][0], ql[mt][1], ql[mt][2], ql[mt][3], uQl + off);
                }
                uint32_t kh[4][4], kl[4][4];
#pragma unroll
                for (int nt2 = 0; nt2 < 4; nt2++) {
                    uint32_t off = ((nt2*16 + b_r) * ALD + kk + b_c) * 2;
                    ldsm_x4(kh[nt2][0], kh[nt2][1], kh[nt2][2], kh[nt2][3], uKh + off);
                    ldsm_x4(kl[nt2][0], kl[nt2][1], kl[nt2][2], kl[nt2][3], uKl + off);
                }
#pragma unroll
                for (int mt = 0; mt < 2; mt++) {
#pragma unroll
                    for (int nt2 = 0; nt2 < 4; nt2++) {
                        float* d0 = s[mt][2*nt2];
                        float* d1 = s[mt][2*nt2+1];
                        mma_bf16(d0[0],d0[1],d0[2],d0[3],
                                 qh[mt][0],qh[mt][1],qh[mt][2],qh[mt][3],
                                 kh[nt2][0],kh[nt2][1]);
                        mma_bf16(d1[0],d1[1],d1[2],d1[3],
                                 qh[mt][0],qh[mt][1],qh[mt][2],qh[mt][3],
                                 kh[nt2][2],kh[nt2][3]);
                        mma_bf16(d0[0],d0[1],d0[2],d0[3],
                                 qh[mt][0],qh[mt][1],qh[mt][2],qh[mt][3],
                                 kl[nt2][0],kl[nt2][1]);
                        mma_bf16(d1[0],d1[1],d1[2],d1[3],
                                 qh[mt][0],qh[mt][1],qh[mt][2],qh[mt][3],
                                 kl[nt2][2],kl[nt2][3]);
                        mma_bf16(d0[0],d0[1],d0[2],d0[3],
                                 ql[mt][0],ql[mt][1],ql[mt][2],ql[mt][3],
                                 kh[nt2][0],kh[nt2][1]);
                        mma_bf16(d1[0],d1[1],d1[2],d1[3],
                                 ql[mt][0],ql[mt][1],ql[mt][2],ql[mt][3],
                                 kh[nt2][2],kh[nt2][3]);
                    }
                }
            }

            if (kb + 63 > q0) {
#pragma unroll
                for (int mt = 0; mt < 2; mt++) {
                    const int r0 = q0 + mt*16 + lr;
#pragma unroll
                    for (int nt = 0; nt < 8; nt++) {
                        const int c0 = kb + nt*8 + lc2;
                        if (c0     > r0)     s[mt][nt][0] = NEG_INF;
                        if (c0 + 1 > r0)     s[mt][nt][1] = NEG_INF;
                        if (c0     > r0 + 8) s[mt][nt][2] = NEG_INF;
                        if (c0 + 1 > r0 + 8) s[mt][nt][3] = NEG_INF;
                    }
                }
            }

            float alpha[4];
#pragma unroll
            for (int mt = 0; mt < 2; mt++) {
#pragma unroll
                for (int hh = 0; hh < 2; hh++) {
                    const int e0 = hh*2;
                    const int id = mt*2 + hh;
                    float mx = NEG_INF;
#pragma unroll
                    for (int nt = 0; nt < 8; nt++)
                        mx = fmaxf(mx, fmaxf(s[mt][nt][e0], s[mt][nt][e0+1]));
                    mx = fmaxf(mx, __shfl_xor_sync(0xffffffffu, mx, 1));
                    mx = fmaxf(mx, __shfl_xor_sync(0xffffffffu, mx, 2));
                    const float mnew = fmaxf(mrow[id], mx);
                    const float al = ex2f(mrow[id] - mnew);
                    mrow[id] = mnew;
                    float ls = 0.0f;
#pragma unroll
                    for (int nt = 0; nt < 8; nt++) {
                        float p0 = ex2f(s[mt][nt][e0]   - mnew);
                        float p1 = ex2f(s[mt][nt][e0+1] - mnew);
                        s[mt][nt][e0]   = p0;
                        s[mt][nt][e0+1] = p1;
                        ls += p0 + p1;
                    }
                    ls += __shfl_xor_sync(0xffffffffu, ls, 1);
                    ls += __shfl_xor_sync(0xffffffffu, ls, 2);
                    lrow[id] = lrow[id] * al + ls;
                    alpha[id] = al;
                }
            }
#pragma unroll
            for (int mt = 0; mt < 2; mt++)
#pragma unroll
                for (int nt = 0; nt < 8; nt++) {
                    o[mt][nt][0] *= alpha[mt*2];
                    o[mt][nt][1] *= alpha[mt*2];
                    o[mt][nt][2] *= alpha[mt*2+1];
                    o[mt][nt][3] *= alpha[mt*2+1];
                }

#pragma unroll
            for (int kk = 0; kk < 4; kk++) {
                uint32_t vh[4][4], vl[4][4];
#pragma unroll
                for (int nt2 = 0; nt2 < 4; nt2++) {
                    uint32_t off = ((nt2*16 + b_r) * ALD + kk*16 + b_c) * 2;
                    ldsm_x4(vh[nt2][0], vh[nt2][1], vh[nt2][2], vh[nt2][3], uVh + off);
                    ldsm_x4(vl[nt2][0], vl[nt2][1], vl[nt2][2], vl[nt2][3], uVl + off);
                }
#pragma unroll
                for (int mt = 0; mt < 2; mt++) {
                    uint32_t ph[4], pl[4];
                    split2(s[mt][2*kk][0],   s[mt][2*kk][1],   ph[0], pl[0]);
                    split2(s[mt][2*kk][2],   s[mt][2*kk][3],   ph[1], pl[1]);
                    split2(s[mt][2*kk+1][0], s[mt][2*kk+1][1], ph[2], pl[2]);
                    split2(s[mt][2*kk+1][2], s[mt][2*kk+1][3], ph[3], pl[3]);
#pragma unroll
                    for (int nt2 = 0; nt2 < 4; nt2++) {
                        float* d0 = o[mt][2*nt2];
                        float* d1 = o[mt][2*nt2+1];
                        mma_bf16(d0[0],d0[1],d0[2],d0[3],
                                 ph[0],ph[1],ph[2],ph[3],
                                 vh[nt2][0],vh[nt2][1]);
                        mma_bf16(d1[0],d1[1],d1[2],d1[3],
                                 ph[0],ph[1],ph[2],ph[3],
                                 vh[nt2][2],vh[nt2][3]);
                        mma_bf16(d0[0],d0[1],d0[2],d0[3],
                                 ph[0],ph[1],ph[2],ph[3],
                                 vl[nt2][0],vl[nt2][1]);
                        mma_bf16(d1[0],d1[1],d1[2],d1[3],
                                 ph[0],ph[1],ph[2],ph[3],
                                 vl[nt2][2],vl[nt2][3]);
                        mma_bf16(d0[0],d0[1],d0[2],d0[3],
                                 pl[0],pl[1],pl[2],pl[3],
                                 vh[nt2][0],vh[nt2][1]);
                        mma_bf16(d1[0],d1[1],d1[2],d1[3],
                                 pl[0],pl[1],pl[2],pl[3],
                                 vh[nt2][2],vh[nt2][3]);
                    }
                }
            }
        }
        __syncthreads();
    }

    // ---- normalize + split-write O directly as proj's A operand ----
#pragma unroll
    for (int mt = 0; mt < 2; mt++) {
#pragma unroll
        for (int hh = 0; hh < 2; hh++) {
            const float inv = 1.0f / lrow[mt*2 + hh];
            const int row = qt*128 + wm*32 + mt*16 + lr + hh*8;
            const size_t base = ((size_t)(b*TLEN + row))*CDIM + h*64;
#pragma unroll
            for (int nt = 0; nt < 8; nt++) {
                uint32_t hi, lo;
                split2(o[mt][nt][hh*2] * inv, o[mt][nt][hh*2+1] * inv, hi, lo);
                *reinterpret_cast<uint32_t*>(yh + base + nt*8 + lc2) = hi;
                *reinterpret_cast<uint32_t*>(yl + base + nt*8 + lc2) = lo;
            }
        }
    }
}

// ---------------------------------------------------------------------------
// Launch
// ---------------------------------------------------------------------------
extern "C" void kernel_launch(void* const* d_in, const int* in_sizes, int n_in,
                              void* d_out, int out_size)
{
    (void)in_sizes; (void)n_in; (void)out_size;
    const float* x      = (const float*)d_in[0];
    const float* W_attn = (const float*)d_in[1];
    const float* b_attn = (const float*)d_in[2];
    const float* W_proj = (const float*)d_in[3];
    const float* b_proj = (const float*)d_in[4];
    float* out = (float*)d_out;

    float *qkv_ptr;
    __nv_bfloat16 *ah, *al, *wah, *wal, *wph, *wpl;
    __nv_bfloat16 *qh2, *ql2, *kh2, *kl2, *vth, *vtl;
    cudaGetSymbolAddress((void**)&qkv_ptr, g_qkv);
    cudaGetSymbolAddress((void**)&ah,  g_ah);
    cudaGetSymbolAddress((void**)&al,  g_al);
    cudaGetSymbolAddress((void**)&wah, g_wah);
    cudaGetSymbolAddress((void**)&wal, g_wal);
    cudaGetSymbolAddress((void**)&wph, g_wph);
    cudaGetSymbolAddress((void**)&wpl, g_wpl);
    cudaGetSymbolAddress((void**)&qh2, g_qh2);
    cudaGetSymbolAddress((void**)&ql2, g_ql2);
    cudaGetSymbolAddress((void**)&kh2, g_kh2);
    cudaGetSymbolAddress((void**)&kl2, g_kl2);
    cudaGetSymbolAddress((void**)&vth, g_vth);
    cudaGetSymbolAddress((void**)&vtl, g_vtl);

    static bool attr_set = false;
    if (!attr_set) {
        cudaFuncSetAttribute(gemm_hmma_kernel,
                             cudaFuncAttributeMaxDynamicSharedMemorySize,
                             GEMM_SMEM_BYTES);
        cudaFuncSetAttribute(attn_mma_kernel,
                             cudaFuncAttributeMaxDynamicSharedMemorySize,
                             ATTN_SMEM_BYTES);
        attr_set = true;
    }

    const int M = MROWS;

    // Prep: split x; transpose+split weights
    {
        int n4 = M * CDIM / 4;
        split_kernel<<<(n4 + 255)/256, 256>>>(x, ah, al, n4);
        dim3 tb(32, 8);
        transpose_split_kernel<<<dim3(3*CDIM/32, CDIM/32), tb>>>(W_attn, wah, wal, CDIM, 3*CDIM);
        transpose_split_kernel<<<dim3(CDIM/32, CDIM/32), tb>>>(W_proj, wph, wpl, CDIM, CDIM);
    }

    // 1) QKV GEMM
    gemm_hmma_kernel<<<dim3(3*CDIM/128, M/128), 128, GEMM_SMEM_BYTES>>>(
        ah, al, wah, wal, b_attn, qkv_ptr, 3*CDIM, CDIM);

    // 2) attention prep
    {
        int n = BSZ*TLEN*2*HN*16;
        split_qk_kernel<<<(n + 255)/256, 256>>>(qkv_ptr, qh2, ql2, kh2, kl2);
        dim3 tb(32, 8);
        transpose_split_v_kernel<<<dim3(BSZ*HN, TLEN/32, 2), tb>>>(qkv_ptr, vth, vtl);
    }

    // 3) flash attention (HMMA, cp.async K/V loads) -> split O into (g_ah, g_al)
    attn_mma_kernel<<<dim3(TLEN/128, BSZ*HN), 128, ATTN_SMEM_BYTES>>>(
        qh2, ql2, kh2, kl2, vth, vtl, ah, al);

    // 4) proj GEMM (full K, bias)
    gemm_hmma_kernel<<<dim3(CDIM/128, M/128), 128, GEMM_SMEM_BYTES>>>(
        ah, al, wph, wpl, b_proj, out, CDIM, CDIM);
}